// round 12
// baseline (speedup 1.0000x reference)
#include <cuda_runtime.h>

// RMAC max-pooling, x: (64, 37, 37, 512) f32 NHWC -> out: (64, 14, 512) f32.
// Regions = products of 6 x-intervals and 6 y-intervals:
//   0:[0,37) 1:[0,24) 2:[13,37) 3:[0,18) 4:[9,27) 5:[19,37)
//   r0:(y0,x0) r1:(y1,x1) r2:(y1,x2) r3:(y2,x1) r4:(y2,x2)
//   r5-7:(y3,x3/4/5) r8-10:(y4,x3/4/5) r11-13:(y5,x3/4/5)
//
// R12: single fused kernel (R8/R11 proved the 2nd kernel's ~4.5us fixed cost
// is unavoidable otherwise; R7's fused attempt lost to 128-thread threadfence
// and a 29MB finisher table). Grid (17,64,2) x 64 thr = 2176 blocks = 14.7
// waves (R6's 7.35-wave grid paid ~3us fractional tail). Stream body = R6 K1.
// Completion: syncthreads -> tid0-only threadfence + atomicAdd per
// (batch, ch-half); the 17th block finishes that batch-half: reads its 104KB
// of L2-hot table and writes the 14 region outputs. Early-batch finishers
// overlap the stream; only the last one (~1.5us) is exposed.

#define NEG_INF __int_as_float(0xff800000)
#define NSUB 17

// Partial table: [64][6 x-intervals][17 sub-bands][512 ch] = 13.4 MB.
__device__ float g_P[64 * 6 * NSUB * 512];
// Arrival counters per (batch, channel-half). Zero-init; finisher resets.
__device__ int g_cnt[64 * 2];

__constant__ int c_sstart[NSUB] = {0, 2, 4, 7, 9, 11, 13, 15, 18, 19, 20, 22, 24, 27, 29, 32, 34};
__constant__ int c_slen[NSUB]   = {2, 2, 3, 2, 2, 2, 2, 3, 1, 1, 2, 2, 3, 2, 3, 2, 3};

__device__ __forceinline__ float4 fmax4(float4 a, float4 b) {
    return make_float4(fmaxf(a.x, b.x), fmaxf(a.y, b.y),
                       fmaxf(a.z, b.z), fmaxf(a.w, b.w));
}

__global__ __launch_bounds__(64) void rmac_fused(const float* __restrict__ x,
                                                 float* __restrict__ out) {
    const int s    = blockIdx.x;                     // sub-band 0..16
    const int b    = blockIdx.y;                     // batch
    const int half = blockIdx.z;                     // channel half
    const int c4   = half * 64 + threadIdx.x;        // float4 ch idx 0..127

    const float4* __restrict__ x4 = (const float4*)x;
    const float4 ninf = make_float4(NEG_INF, NEG_INF, NEG_INF, NEG_INF);

    // ── Stream this sub-band's rows (R6 K1 body) ──
    float4 s0 = ninf, s1 = ninf, s2 = ninf, s3 = ninf,
           s4 = ninf, s5 = ninf, s6 = ninf;

    const int h0  = c_sstart[s];
    const int len = c_slen[s];

    for (int hh = 0; hh < len; ++hh) {
        const int h = h0 + hh;
        size_t rb = ((size_t)(b * 37 + h) * 37) * 128 + c4;
#pragma unroll
        for (int w = 0; w < 37; ++w) {
            float4 v = x4[rb + (size_t)w * 128];
            if      (w <  9) s0 = fmax4(s0, v);
            else if (w < 13) s1 = fmax4(s1, v);
            else if (w < 18) s2 = fmax4(s2, v);
            else if (w < 19) s3 = fmax4(s3, v);
            else if (w < 24) s4 = fmax4(s4, v);
            else if (w < 27) s5 = fmax4(s5, v);
            else             s6 = fmax4(s6, v);
        }
    }

    // 7 w-segments -> 6 x-interval maxes.
    float4 I3 = fmax4(fmax4(s0, s1), s2);                        // [0,18)
    float4 I1 = fmax4(fmax4(I3, s3), s4);                        // [0,24)
    float4 I5 = fmax4(fmax4(s4, s5), s6);                        // [19,37)
    float4 I0 = fmax4(I1, fmax4(s5, s6));                        // [0,37)
    float4 I2 = fmax4(fmax4(s2, s3), I5);                        // [13,37)
    float4 I4 = fmax4(fmax4(s1, s2), fmax4(s3, fmax4(s4, s5)));  // [9,27)

    // Table [b][i][s][512].
    float4* P4 = (float4*)g_P;
    size_t base = ((size_t)(b * 6) * NSUB + s) * 128 + c4;
    P4[base + (size_t)(0 * NSUB) * 128] = I0;
    P4[base + (size_t)(1 * NSUB) * 128] = I1;
    P4[base + (size_t)(2 * NSUB) * 128] = I2;
    P4[base + (size_t)(3 * NSUB) * 128] = I3;
    P4[base + (size_t)(4 * NSUB) * 128] = I4;
    P4[base + (size_t)(5 * NSUB) * 128] = I5;

    // ── Completion: one fence + one atomic per block (tid0 only) ──
    __syncthreads();                 // orders all threads' table stores
    __shared__ int isLast;
    if (threadIdx.x == 0) {
        __threadfence();             // release: table visible at gpu scope
        int old = atomicAdd(&g_cnt[b * 2 + half], 1);
        isLast = (old == NSUB - 1);
    }
    __syncthreads();
    if (!isLast) return;

    // ── Finisher for (b, half): acquire, then reduce the L2-hot table ──
    __threadfence();                 // acquire side
    const float4* __restrict__ Pr = (const float4*)g_P;
    float4* O4 = (float4*)out;
    const size_t ob = (size_t)b * 14 * 128 + c4;

    // i=0 -> r0 (full y)
    {
        float4 a = ninf;
        size_t tbase = ((size_t)(b * 6 + 0) * NSUB) * 128 + c4;
#pragma unroll
        for (int t = 0; t < NSUB; ++t) a = fmax4(a, Pr[tbase + (size_t)t * 128]);
        O4[ob + 0 * 128] = a;
    }
    // i=1 -> r1 (y1: s<=11), r3 (y2: s>=6);  i=2 -> r2, r4
#pragma unroll
    for (int i = 1; i <= 2; ++i) {
        float4 a1 = ninf, a2 = ninf;
        size_t tbase = ((size_t)(b * 6 + i) * NSUB) * 128 + c4;
#pragma unroll
        for (int t = 0; t < NSUB; ++t) {
            float4 v = Pr[tbase + (size_t)t * 128];
            if (t <= 11) a1 = fmax4(a1, v);
            if (t >= 6)  a2 = fmax4(a2, v);
        }
        O4[ob + (size_t)(i == 1 ? 1 : 2) * 128] = a1;
        O4[ob + (size_t)(i == 1 ? 3 : 4) * 128] = a2;
    }
    // i=3/4/5 -> (y3: s<=7, y4: 4<=s<=12, y5: s>=9) = r5-7 / r8-10 / r11-13
#pragma unroll
    for (int i = 3; i <= 5; ++i) {
        float4 a3 = ninf, a4 = ninf, a5 = ninf;
        size_t tbase = ((size_t)(b * 6 + i) * NSUB) * 128 + c4;
#pragma unroll
        for (int t = 0; t < NSUB; ++t) {
            float4 v = Pr[tbase + (size_t)t * 128];
            if (t <= 7)            a3 = fmax4(a3, v);
            if (t >= 4 && t <= 12) a4 = fmax4(a4, v);
            if (t >= 9)            a5 = fmax4(a5, v);
        }
        O4[ob + (size_t)(5  + (i - 3)) * 128] = a3;
        O4[ob + (size_t)(8  + (i - 3)) * 128] = a4;
        O4[ob + (size_t)(11 + (i - 3)) * 128] = a5;
    }

    // Reset counter for the next graph replay.
    if (threadIdx.x == 0) g_cnt[b * 2 + half] = 0;
}

extern "C" void kernel_launch(void* const* d_in, const int* in_sizes, int n_in,
                              void* d_out, int out_size) {
    const float* x = (const float*)d_in[0];
    float* out = (float*)d_out;

    rmac_fused<<<dim3(NSUB, 64, 2), 64>>>(x, out);
}